// round 4
// baseline (speedup 1.0000x reference)
#include <cuda_runtime.h>
#include <math.h>

#define NT 256

// ---------------- shared memory layout (floats) ----------------
constexpr int OFF_F   = 0;      // f:    [6][16][16]            = 1536
constexpr int OFF_RP  = 1536;   // rp:   [6][14][14] padded     = 1176 (reused as zbuf)
constexpr int OFF_HID = 2712;   // hidp: [48][14][14] padded    = 9408
constexpr int OFF_W1  = 12120;  // 48*6 taps padded to 12       = 3456
constexpr int OFF_W2  = 15576;  // 6*48 taps padded to 12       = 3456
constexpr int OFF_B1  = 19032;  // 48
constexpr int OFF_B2  = 19080;  // 8
constexpr int SMEM_FLOATS = 19088;
constexpr int SMEM_BYTES  = SMEM_FLOATS * 4;

// ---------------- XLA-exact tanh (EmitFastTanh rational, verified) ----------------
// |x| < 4e-4 -> x; else clamp +-7.90531110763549805, Eigen rational in x^2.
// Verified: gives 0.76159 @ x=1, 0.96403 @ x=2 (= tanh exactly to f32 precision).
__device__ __forceinline__ float xla_tanh(float x) {
    if (fabsf(x) < 0.0004f) return x;
    float xc = fminf(fmaxf(x, -7.90531110763549805f), 7.90531110763549805f);
    float x2 = __fmul_rn(xc, xc);
    float p = fmaf(x2, -2.76076847742355e-16f, 2.00018790482477e-13f);
    p = fmaf(x2, p, -8.60467152213735e-11f);
    p = fmaf(x2, p,  5.12229709037114e-08f);
    p = fmaf(x2, p,  1.48572235717979e-05f);
    p = fmaf(x2, p,  6.37261928875436e-04f);
    p = fmaf(x2, p,  4.89352455891786e-03f);
    p = __fmul_rn(xc, p);
    float q = fmaf(x2, 1.19825839466702e-06f, 1.18534705686654e-04f);
    q = fmaf(x2, q, 2.26843463243900e-03f);
    q = fmaf(x2, q, 4.89352518554385e-03f);
    return __fdiv_rn(p, q);
}

// jax.nn.gelu(approximate=False): (x * (erf(x / f32(sqrt(2))) + 1)) / 2
// erff is <=2ulp of true erf; XLA's poly is ~1ulp -> residual mismatch ~3ulp (continuous).
__device__ __forceinline__ float gelu_exact(float x) {
    float t = __fdiv_rn(x, 1.4142135623730951f);
    float e = erff(t);
    return __fmul_rn(__fmul_rn(x, __fadd_rn(e, 1.0f)), 0.5f);
}

// jax.image.resize bilinear coefficients, exact arithmetic:
// multiplier = f32(f64(IN)/f64(OUT)); s = (o+0.5)*inv - 0.5 (mul then sub, no fma);
// taps k0 = 1-(s-fl), k1 = 1-((fl+1)-s) (mirrors jnp 1-abs ops), zero out-of-range,
// normalize each tap by (k0+k1).
template<int IN, int OUT>
__device__ __forceinline__ void lin_coef(int o, int& i0, int& i1, float& w0, float& w1) {
    constexpr float INV = (float)((double)IN / (double)OUT);
    float s  = __fadd_rn(__fmul_rn(__fadd_rn((float)o, 0.5f), INV), -0.5f);
    float fl = floorf(s);
    int a0 = (int)fl, a1 = a0 + 1;
    float k0 = __fadd_rn(1.0f, -__fadd_rn(s, -fl));                   // 1 - (s - fl)
    float k1 = __fadd_rn(1.0f, -__fadd_rn(__fadd_rn(fl, 1.0f), -s)); // 1 - ((fl+1) - s)
    if (a0 < 0)      { k0 = 0.0f; a0 = 0; }
    if (a1 > IN - 1) { k1 = 0.0f; a1 = IN - 1; }
    float S = __fadd_rn(k0, k1);
    i0 = a0; i1 = a1;
    w0 = __fdiv_rn(k0, S);
    w1 = __fdiv_rn(k1, S);
}

// FSQ quantize, levels [8,8,8,5,5,5], eps=1e-3, jax op order (no fma contraction)
__device__ __forceinline__ float fsq_q(float z, int c, float shift8) {
    constexpr float HL8 = (8.0f - 1.0f) * 1.0010000467300415039f / 2.0f;
    constexpr float HL5 = (5.0f - 1.0f) * 1.0010000467300415039f / 2.0f;
    if (c < 3) {
        float b = __fadd_rn(__fmul_rn(xla_tanh(__fadd_rn(z, shift8)), HL8), -0.5f);
        return __fmul_rn(rintf(b), 0.25f);
    } else {
        float b = __fmul_rn(xla_tanh(z), HL5);
        return __fmul_rn(rintf(b), 0.5f);
    }
}

// 2-tap x 2-tap bilinear apply, h-contraction first, explicit roundings
__device__ __forceinline__ float bilerp(const float* __restrict__ base, int stride,
                                        int iy0, int iy1, int ix0, int ix1,
                                        float wy0, float wy1, float wx0, float wx1) {
    float g0 = __fadd_rn(__fmul_rn(wy0, base[iy0 * stride + ix0]),
                         __fmul_rn(wy1, base[iy1 * stride + ix0]));
    float g1 = __fadd_rn(__fmul_rn(wy0, base[iy0 * stride + ix1]),
                         __fmul_rn(wy1, base[iy1 * stride + ix1]));
    return __fadd_rn(__fmul_rn(wx0, g0), __fmul_rn(wx1, g1));
}

// ---------------- stage a: clear tiles + stage weights ----------------
template<int SI, int H, int W>
__device__ void load_stage(float* __restrict__ sm,
                           const float* __restrict__ w1g, const float* __restrict__ b1g,
                           const float* __restrict__ w2g, const float* __restrict__ b2g,
                           int tid) {
    constexpr int P = (H + 2) * (W + 2);
    for (int i = tid; i < 6 * P; i += NT)  sm[OFF_RP  + i] = 0.0f;
    for (int i = tid; i < 48 * P; i += NT) sm[OFF_HID + i] = 0.0f;
    for (int i = tid; i < 2592; i += NT) {
        int kc = i / 9, q = i - kc * 9;
        sm[OFF_W1 + kc * 12 + q] = w1g[SI * 2592 + i];
        sm[OFF_W2 + kc * 12 + q] = w2g[SI * 2592 + i];
    }
    if (tid < 48) sm[OFF_B1 + tid] = b1g[SI * 48 + tid];
    if (tid < 6)  sm[OFF_B2 + tid] = b2g[SI * 6 + tid];
}

// ---------------- stage b: bilinear resize f -> (H,W), FSQ, emit tokens ----------------
template<int SI, int H, int W>
__device__ void resize_fsq(const float* __restrict__ sm_f, float* __restrict__ rp,
                           float* __restrict__ outp, int tid, float shift8) {
    constexpr int HW = H * W;
    constexpr bool LAST = (SI == 7);
    for (int idx = tid; idx < 6 * HW; idx += NT) {
        int c = idx / HW;
        int p = idx - c * HW;
        int y = p / W, x = p - y * W;
        float v;
        if (H == 16 && W == 16) {
            v = sm_f[c * 256 + p];   // identity resize (jax skips equal dims)
        } else {
            int iy0, iy1, ix0, ix1; float wy0, wy1, wx0, wx1;
            lin_coef<16, H>(y, iy0, iy1, wy0, wy1);
            lin_coef<16, W>(x, ix0, ix1, wx0, wx1);
            v = bilerp(sm_f + c * 256, 16, iy0, iy1, ix0, ix1, wy0, wy1, wx0, wx1);
        }
        float t = fsq_q(v, c, shift8);
        outp[idx] = t;
        if (!LAST) rp[c * (H + 2) * (W + 2) + (y + 1) * (W + 2) + (x + 1)] = t;
    }
}

// ---------------- stage c: conv1 6->48 + GELU ----------------
template<int H, int W>
__device__ void conv1(const float* __restrict__ rp, const float* __restrict__ w1s,
                      const float* __restrict__ b1s, float* __restrict__ hidp, int tid) {
    constexpr int HW = H * W;
    constexpr int P  = (H + 2) * (W + 2);
    constexpr int G  = 10;
    constexpr int NP = (HW + G - 1) / G;
    if (tid >= 240) return;
    int kp = tid / G;
    int g  = tid - kp * G;
    int k0 = kp * 2;

    float a0[NP], a1[NP];
    int   off[NP];
    float bb0 = b1s[k0], bb1 = b1s[k0 + 1];
#pragma unroll
    for (int j = 0; j < NP; j++) {
        int p = g + G * j;
        if (p >= HW) p = HW - 1;
        int y = p / W, x = p - y * W;
        off[j] = y * (W + 2) + x;
        a0[j] = bb0;
        a1[j] = bb1;
    }
#pragma unroll 1
    for (int c = 0; c < 6; c++) {
        const float4* wv0 = reinterpret_cast<const float4*>(w1s + (k0 * 6 + c) * 12);
        const float4* wv1 = reinterpret_cast<const float4*>(w1s + ((k0 + 1) * 6 + c) * 12);
        float4 u0 = wv0[0], u1 = wv0[1], u2 = wv0[2];
        float4 v0 = wv1[0], v1 = wv1[1], v2 = wv1[2];
        const float* rb = rp + c * P;
#pragma unroll
        for (int j = 0; j < NP; j++) {
            int o = off[j];
            float r0 = rb[o],              r1 = rb[o + 1],          r2 = rb[o + 2];
            float r3 = rb[o + W + 2],      r4 = rb[o + W + 3],      r5 = rb[o + W + 4];
            float r6 = rb[o + 2 * W + 4],  r7 = rb[o + 2 * W + 5],  r8 = rb[o + 2 * W + 6];
            a0[j] += u0.x * r0 + u0.y * r1 + u0.z * r2
                   + u0.w * r3 + u1.x * r4 + u1.y * r5
                   + u1.z * r6 + u1.w * r7 + u2.x * r8;
            a1[j] += v0.x * r0 + v0.y * r1 + v0.z * r2
                   + v0.w * r3 + v1.x * r4 + v1.y * r5
                   + v1.z * r6 + v1.w * r7 + v2.x * r8;
        }
    }
#pragma unroll
    for (int j = 0; j < NP; j++) {
        int p = g + G * j;
        if (p < HW) {
            int dst = off[j] + (W + 3);
            hidp[k0 * P + dst]       = gelu_exact(a0[j]);
            hidp[(k0 + 1) * P + dst] = gelu_exact(a1[j]);
        }
    }
}

// ---------------- stage d: conv2 48->6 ----------------
template<int H, int W>
__device__ void conv2(const float* __restrict__ hidp, const float* __restrict__ w2s,
                      const float* __restrict__ b2s, float* __restrict__ zbuf, int tid) {
    constexpr int HW = H * W;
    constexpr int P  = (H + 2) * (W + 2);
    constexpr int G  = 85;
    constexpr int NP = (HW + G - 1) / G;
    if (tid >= 255) return;
    int kp = tid / G;
    int g  = tid - kp * G;
    int k0 = kp * 2;

    float a0[NP], a1[NP];
    int   off[NP];
    float bb0 = b2s[k0], bb1 = b2s[k0 + 1];
#pragma unroll
    for (int j = 0; j < NP; j++) {
        int p = g + G * j;
        if (p >= HW) p = HW - 1;
        int y = p / W, x = p - y * W;
        off[j] = y * (W + 2) + x;
        a0[j] = bb0;
        a1[j] = bb1;
    }
#pragma unroll 1
    for (int c = 0; c < 48; c++) {
        const float4* wv0 = reinterpret_cast<const float4*>(w2s + (k0 * 48 + c) * 12);
        const float4* wv1 = reinterpret_cast<const float4*>(w2s + ((k0 + 1) * 48 + c) * 12);
        float4 u0 = wv0[0], u1 = wv0[1], u2 = wv0[2];
        float4 v0 = wv1[0], v1 = wv1[1], v2 = wv1[2];
        const float* hb = hidp + c * P;
#pragma unroll
        for (int j = 0; j < NP; j++) {
            int o = off[j];
            float r0 = hb[o],              r1 = hb[o + 1],          r2 = hb[o + 2];
            float r3 = hb[o + W + 2],      r4 = hb[o + W + 3],      r5 = hb[o + W + 4];
            float r6 = hb[o + 2 * W + 4],  r7 = hb[o + 2 * W + 5],  r8 = hb[o + 2 * W + 6];
            a0[j] += u0.x * r0 + u0.y * r1 + u0.z * r2
                   + u0.w * r3 + u1.x * r4 + u1.y * r5
                   + u1.z * r6 + u1.w * r7 + u2.x * r8;
            a1[j] += v0.x * r0 + v0.y * r1 + v0.z * r2
                   + v0.w * r3 + v1.x * r4 + v1.y * r5
                   + v1.z * r6 + v1.w * r7 + v2.x * r8;
        }
    }
#pragma unroll
    for (int j = 0; j < NP; j++) {
        int p = g + G * j;
        if (p < HW) {
            zbuf[k0 * HW + p]       = a0[j];
            zbuf[(k0 + 1) * HW + p] = a1[j];
        }
    }
}

// ---------------- stage e: upsample z (H,W)->(16,16), f -= z ----------------
template<int H, int W>
__device__ void upsub(float* __restrict__ sm_f, const float* __restrict__ zbuf, int tid) {
    constexpr int HW = H * W;
    for (int idx = tid; idx < 1536; idx += NT) {
        int c = idx >> 8;
        int p = idx & 255;
        int Y = p >> 4, X = p & 15;
        int iy0, iy1, ix0, ix1; float wy0, wy1, wx0, wx1;
        lin_coef<H, 16>(Y, iy0, iy1, wy0, wy1);
        lin_coef<W, 16>(X, ix0, ix1, wx0, wx1);
        float v = bilerp(zbuf + c * HW, W, iy0, iy1, ix0, ix1, wy0, wy1, wx0, wx1);
        sm_f[idx] = __fadd_rn(sm_f[idx], -v);
    }
}

// ---------------- one scale ----------------
template<int SI, int H, int W>
__device__ void do_scale(float* __restrict__ sm,
                         const float* __restrict__ w1g, const float* __restrict__ b1g,
                         const float* __restrict__ w2g, const float* __restrict__ b2g,
                         float* __restrict__ outp, int tid, float shift8) {
    constexpr bool LAST = (SI == 7);
    if (!LAST) {
        load_stage<SI, H, W>(sm, w1g, b1g, w2g, b2g, tid);
        __syncthreads();
    }
    resize_fsq<SI, H, W>(sm + OFF_F, sm + OFF_RP, outp, tid, shift8);
    if (LAST) return;
    __syncthreads();
    conv1<H, W>(sm + OFF_RP, sm + OFF_W1, sm + OFF_B1, sm + OFF_HID, tid);
    __syncthreads();
    conv2<H, W>(sm + OFF_HID, sm + OFF_W2, sm + OFF_B2, sm + OFF_RP /*zbuf alias*/, tid);
    __syncthreads();
    upsub<H, W>(sm + OFF_F, sm + OFF_RP, tid);
    __syncthreads();
}

__global__ void __launch_bounds__(NT, 2)
var_tokenizer_kernel(const float* __restrict__ lat,
                     const float* __restrict__ w1, const float* __restrict__ b1,
                     const float* __restrict__ w2, const float* __restrict__ b2,
                     float* __restrict__ out) {
    extern __shared__ float sm[];
    int b   = blockIdx.x;
    int tid = threadIdx.x;

    const float4* src  = reinterpret_cast<const float4*>(lat + (size_t)b * 1536);
    float4*       dstf = reinterpret_cast<float4*>(sm + OFF_F);
    for (int i = tid; i < 384; i += NT) dstf[i] = src[i];

    // shift8 = arctanh(0.5f / half_l8): f32 ratio, high-precision atanh, round to f32
    constexpr float HL8 = (8.0f - 1.0f) * 1.0010000467300415039f / 2.0f;
    float ratio = __fdiv_rn(0.5f, HL8);
    float shift8 = (float)atanh((double)ratio);

    float* outb = out + (size_t)b * 3726;
    __syncthreads();

    do_scale<0, 1, 1>  (sm, w1, b1, w2, b2, outb + 0,    tid, shift8);
    do_scale<1, 2, 2>  (sm, w1, b1, w2, b2, outb + 6,    tid, shift8);
    do_scale<2, 4, 4>  (sm, w1, b1, w2, b2, outb + 30,   tid, shift8);
    do_scale<3, 6, 6>  (sm, w1, b1, w2, b2, outb + 126,  tid, shift8);
    do_scale<4, 8, 8>  (sm, w1, b1, w2, b2, outb + 342,  tid, shift8);
    do_scale<5, 10, 10>(sm, w1, b1, w2, b2, outb + 726,  tid, shift8);
    do_scale<6, 12, 12>(sm, w1, b1, w2, b2, outb + 1326, tid, shift8);
    do_scale<7, 16, 16>(sm, w1, b1, w2, b2, outb + 2190, tid, shift8);
}

extern "C" void kernel_launch(void* const* d_in, const int* in_sizes, int n_in,
                              void* d_out, int out_size) {
    const float* lat = (const float*)d_in[0];
    const float* w1  = (const float*)d_in[1];
    const float* b1  = (const float*)d_in[2];
    const float* w2  = (const float*)d_in[3];
    const float* b2  = (const float*)d_in[4];
    float* out = (float*)d_out;

    int B = in_sizes[0] / 1536;

    cudaFuncSetAttribute(var_tokenizer_kernel,
                         cudaFuncAttributeMaxDynamicSharedMemorySize, SMEM_BYTES);
    var_tokenizer_kernel<<<B, NT, SMEM_BYTES>>>(lat, w1, b1, w2, b2, out);
}

// round 6
// speedup vs baseline: 1.0317x; 1.0317x over previous
#include <cuda_runtime.h>
#include <math.h>

#define NT 256
typedef unsigned long long u64;

// ---------------- shared memory layout (floats) ----------------
constexpr int OFF_F    = 0;      // f:    [6][16][16]                 = 1536
constexpr int OFF_RP   = 1536;   // rp:   [6][(H+2)(W+2)] max 6*196   = 1176 (reused as zbuf [6][HW])
constexpr int OFF_HID  = 2712;   // hidp: [48][(H+2)(W+2)] max        = 9408
constexpr int OFF_W1P  = 12120;  // conv1 weights dup-packed f32x2: [k48][c6][dy3][4] +1 pad/k = 48*73 f32x2 = 7008
constexpr int OFF_W2P  = 19128;  // conv2 weights dup-packed f32x2: [k6][c48][dy3][4] +1 pad/k = 6*577 f32x2 = 6924
constexpr int OFF_B1   = 26052;  // 48
constexpr int OFF_B2   = 26100;  // 8
constexpr int SMEM_FLOATS = 26108;
constexpr int SMEM_BYTES  = SMEM_FLOATS * 4;   // 104432 B -> 2 blocks/SM

constexpr int S1K = 73;   // conv1 per-k stride in f32x2 (6*12 + 1 pad)
constexpr int S2K = 577;  // conv2 per-k stride in f32x2 (48*12 + 1 pad)

// ---------------- f32x2 packed helpers ----------------
__device__ __forceinline__ u64 pack2(float lo, float hi) {
    u64 r; asm("mov.b64 %0, {%1, %2};" : "=l"(r) : "f"(lo), "f"(hi)); return r;
}
__device__ __forceinline__ void unpack2(u64 v, float& lo, float& hi) {
    asm("mov.b64 {%0, %1}, %2;" : "=f"(lo), "=f"(hi) : "l"(v));
}
// d = a*b + d, two independent IEEE rn FMAs (bit-identical to scalar fmaf per lane)
__device__ __forceinline__ void fma2(u64& d, u64 a, u64 b) {
    asm("fma.rn.f32x2 %0, %1, %2, %0;" : "+l"(d) : "l"(a), "l"(b));
}
__device__ __forceinline__ u64 lds2(const float* p) {
    return *reinterpret_cast<const u64*>(p);
}

// ---------------- XLA-exact tanh (verified bit-exact in round 4) ----------------
__device__ __forceinline__ float xla_tanh(float x) {
    if (fabsf(x) < 0.0004f) return x;
    float xc = fminf(fmaxf(x, -7.90531110763549805f), 7.90531110763549805f);
    float x2 = __fmul_rn(xc, xc);
    float p = fmaf(x2, -2.76076847742355e-16f, 2.00018790482477e-13f);
    p = fmaf(x2, p, -8.60467152213735e-11f);
    p = fmaf(x2, p,  5.12229709037114e-08f);
    p = fmaf(x2, p,  1.48572235717979e-05f);
    p = fmaf(x2, p,  6.37261928875436e-04f);
    p = fmaf(x2, p,  4.89352455891786e-03f);
    p = __fmul_rn(xc, p);
    float q = fmaf(x2, 1.19825839466702e-06f, 1.18534705686654e-04f);
    q = fmaf(x2, q, 2.26843463243900e-03f);
    q = fmaf(x2, q, 4.89352518554385e-03f);
    return __fdiv_rn(p, q);
}

__device__ __forceinline__ float gelu_exact(float x) {
    float t = __fdiv_rn(x, 1.4142135623730951f);
    float e = erff(t);
    return __fmul_rn(__fmul_rn(x, __fadd_rn(e, 1.0f)), 0.5f);
}

template<int IN, int OUT>
__device__ __forceinline__ void lin_coef(int o, int& i0, int& i1, float& w0, float& w1) {
    constexpr float INV = (float)((double)IN / (double)OUT);
    float s  = __fadd_rn(__fmul_rn(__fadd_rn((float)o, 0.5f), INV), -0.5f);
    float fl = floorf(s);
    int a0 = (int)fl, a1 = a0 + 1;
    float k0 = __fadd_rn(1.0f, -__fadd_rn(s, -fl));
    float k1 = __fadd_rn(1.0f, -__fadd_rn(__fadd_rn(fl, 1.0f), -s));
    if (a0 < 0)      { k0 = 0.0f; a0 = 0; }
    if (a1 > IN - 1) { k1 = 0.0f; a1 = IN - 1; }
    float S = __fadd_rn(k0, k1);
    i0 = a0; i1 = a1;
    w0 = __fdiv_rn(k0, S);
    w1 = __fdiv_rn(k1, S);
}

__device__ __forceinline__ float fsq_q(float z, int c, float shift8) {
    constexpr float HL8 = (8.0f - 1.0f) * 1.0010000467300415039f / 2.0f;
    constexpr float HL5 = (5.0f - 1.0f) * 1.0010000467300415039f / 2.0f;
    if (c < 3) {
        float b = __fadd_rn(__fmul_rn(xla_tanh(__fadd_rn(z, shift8)), HL8), -0.5f);
        return __fmul_rn(rintf(b), 0.25f);
    } else {
        float b = __fmul_rn(xla_tanh(z), HL5);
        return __fmul_rn(rintf(b), 0.5f);
    }
}

__device__ __forceinline__ float bilerp(const float* __restrict__ base, int stride,
                                        int iy0, int iy1, int ix0, int ix1,
                                        float wy0, float wy1, float wx0, float wx1) {
    float g0 = __fadd_rn(__fmul_rn(wy0, base[iy0 * stride + ix0]),
                         __fmul_rn(wy1, base[iy1 * stride + ix0]));
    float g1 = __fadd_rn(__fmul_rn(wy0, base[iy0 * stride + ix1]),
                         __fmul_rn(wy1, base[iy1 * stride + ix1]));
    return __fadd_rn(__fmul_rn(wx0, g0), __fmul_rn(wx1, g1));
}

// ---------------- stage a: clear tiles + stage dup-packed weights ----------------
template<int SI, int H, int W>
__device__ void load_stage(float* __restrict__ sm,
                           const float* __restrict__ w1g, const float* __restrict__ b1g,
                           const float* __restrict__ w2g, const float* __restrict__ b2g,
                           int tid) {
    constexpr int P = (H + 2) * (W + 2);
    if constexpr (H == 1) {
        for (int i = tid; i < 6 * P; i += NT)  sm[OFF_RP  + i] = 0.0f;
        for (int i = tid; i < 48 * P; i += NT) sm[OFF_HID + i] = 0.0f;
    } else {
        float4 z4 = make_float4(0.f, 0.f, 0.f, 0.f);
        float4* rp4 = reinterpret_cast<float4*>(sm + OFF_RP);
        float4* hp4 = reinterpret_cast<float4*>(sm + OFF_HID);
        for (int i = tid; i < 6 * P / 4; i += NT)  rp4[i] = z4;
        for (int i = tid; i < 48 * P / 4; i += NT) hp4[i] = z4;
    }
    // conv1 weights: w1g [48][6][3][3] -> [k][c][dy][4] f32x2 dup
    for (int i = tid; i < 2592; i += NT) {
        int k = i / 54, rm = i - k * 54;
        int c = rm / 9, t = rm - c * 9;
        float v = w1g[SI * 2592 + i];
        int dst = k * S1K + c * 12 + (t / 3) * 4 + (t % 3);
        *reinterpret_cast<float2*>(sm + OFF_W1P + dst * 2) = make_float2(v, v);
    }
    // conv2 weights: w2g [6][48][3][3] -> [k][c][dy][4] f32x2 dup
    for (int i = tid; i < 2592; i += NT) {
        int k = i / 432, rm = i - k * 432;
        int c = rm / 9, t = rm - c * 9;
        float v = w2g[SI * 2592 + i];
        int dst = k * S2K + c * 12 + (t / 3) * 4 + (t % 3);
        *reinterpret_cast<float2*>(sm + OFF_W2P + dst * 2) = make_float2(v, v);
    }
    if (tid < 48) sm[OFF_B1 + tid] = b1g[SI * 48 + tid];
    if (tid < 6)  sm[OFF_B2 + tid] = b2g[SI * 6 + tid];
}

// ---------------- stage b: resize f -> (H,W), FSQ, emit tokens ----------------
template<int SI, int H, int W>
__device__ void resize_fsq(const float* __restrict__ sm_f, float* __restrict__ rp,
                           float* __restrict__ outp, int tid, float shift8) {
    constexpr int HW = H * W;
    constexpr bool LAST = (SI == 7);
    for (int idx = tid; idx < 6 * HW; idx += NT) {
        int c = idx / HW;
        int p = idx - c * HW;
        int y = p / W, x = p - y * W;
        float v;
        if constexpr (H == 16 && W == 16) {
            v = sm_f[c * 256 + p];
        } else {
            int iy0, iy1, ix0, ix1; float wy0, wy1, wx0, wx1;
            lin_coef<16, H>(y, iy0, iy1, wy0, wy1);
            lin_coef<16, W>(x, ix0, ix1, wx0, wx1);
            v = bilerp(sm_f + c * 256, 16, iy0, iy1, ix0, ix1, wy0, wy1, wx0, wx1);
        }
        float t = fsq_q(v, c, shift8);
        outp[idx] = t;
        if (!LAST) rp[c * (H + 2) * (W + 2) + (y + 1) * (W + 2) + (x + 1)] = t;
    }
}

// ---------------- conv1 6->48 + GELU (pixel-pair f32x2 lanes, 2 k per thread) ----------------
template<int H, int W>
__device__ void conv1(float* __restrict__ sm, int tid) {
    constexpr int P  = (H + 2) * (W + 2);
    constexpr int W2 = W + 2;
    constexpr int NS = (24 * H <= NT) ? H : 6;   // row slots
    constexpr int R1 = H / NS;                   // rows per slot (1 or 2)
    constexpr int NPAIR = W / 2;
    if (tid >= 24 * NS) return;
    int kp = tid / NS, slot = tid - kp * NS;
    int k0 = kp * 2;
    const float* rp = sm + OFF_RP;
    const float* wp = sm + OFF_W1P;
    u64 bias0 = pack2(sm[OFF_B1 + k0],     sm[OFF_B1 + k0]);
    u64 bias1 = pack2(sm[OFF_B1 + k0 + 1], sm[OFF_B1 + k0 + 1]);

#pragma unroll 1
    for (int r = 0; r < R1; r++) {
        int y = slot * R1 + r;
        u64 a0[NPAIR], a1[NPAIR];
#pragma unroll
        for (int p = 0; p < NPAIR; p++) { a0[p] = bias0; a1[p] = bias1; }
#pragma unroll 1
        for (int c = 0; c < 6; c++) {
            const float* rb = rp + c * P + y * W2;
            const float* w0 = wp + (k0 * S1K + c * 12) * 2;
            const float* w1 = wp + ((k0 + 1) * S1K + c * 12) * 2;
#pragma unroll
            for (int dy = 0; dy < 3; dy++) {
                const float* rr = rb + dy * W2;
                u64 F[NPAIR + 1];
#pragma unroll
                for (int j = 0; j <= NPAIR; j++) F[j] = lds2(rr + 2 * j);
                u64 t00 = lds2(w0 + (dy * 4 + 0) * 2);
                u64 t01 = lds2(w0 + (dy * 4 + 1) * 2);
                u64 t02 = lds2(w0 + (dy * 4 + 2) * 2);
                u64 t10 = lds2(w1 + (dy * 4 + 0) * 2);
                u64 t11 = lds2(w1 + (dy * 4 + 1) * 2);
                u64 t12 = lds2(w1 + (dy * 4 + 2) * 2);
#pragma unroll
                for (int p = 0; p < NPAIR; p++) {
                    float alo, ahi, blo, bhi;
                    unpack2(F[p], alo, ahi); unpack2(F[p + 1], blo, bhi);
                    u64 M = pack2(ahi, blo);
                    fma2(a0[p], t00, F[p]); fma2(a0[p], t01, M); fma2(a0[p], t02, F[p + 1]);
                    fma2(a1[p], t10, F[p]); fma2(a1[p], t11, M); fma2(a1[p], t12, F[p + 1]);
                }
            }
        }
        float* hp0 = sm + OFF_HID + k0 * P + (y + 1) * W2 + 1;
        float* hp1 = hp0 + P;
#pragma unroll
        for (int p = 0; p < NPAIR; p++) {
            float x0, x1;
            unpack2(a0[p], x0, x1);
            hp0[2 * p] = gelu_exact(x0); hp0[2 * p + 1] = gelu_exact(x1);
            unpack2(a1[p], x0, x1);
            hp1[2 * p] = gelu_exact(x0); hp1[2 * p + 1] = gelu_exact(x1);
        }
    }
}

// conv1 for 1x1 scale: scalar, same tap order
__device__ void conv1_1(float* __restrict__ sm, int tid) {
    if (tid >= 48) return;
    int k = tid;
    const float* rp = sm + OFF_RP;
    const float* wp = sm + OFF_W1P;
    float a = sm[OFF_B1 + k];
#pragma unroll 1
    for (int c = 0; c < 6; c++) {
        const float* rb = rp + c * 9;
        const float* w = wp + (k * S1K + c * 12) * 2;
#pragma unroll
        for (int dy = 0; dy < 3; dy++)
#pragma unroll
            for (int dx = 0; dx < 3; dx++)
                a = fmaf(w[(dy * 4 + dx) * 2], rb[dy * 3 + dx], a);
    }
    sm[OFF_HID + k * 9 + 4] = gelu_exact(a);
}

// ---------------- conv2 48->6 (pixel-pair f32x2 lanes, 1 k per thread, half-rows) ----------------
template<int H, int W, int NP>
__device__ void conv2_half(float* __restrict__ sm, int k, int y, int x0) {
    constexpr int P  = (H + 2) * (W + 2);
    constexpr int W2 = W + 2;
    constexpr int HW = H * W;
    const float* hp = sm + OFF_HID;
    const float* wp = sm + OFF_W2P;
    u64 bias = pack2(sm[OFF_B2 + k], sm[OFF_B2 + k]);
    u64 acc[NP];
#pragma unroll
    for (int p = 0; p < NP; p++) acc[p] = bias;
#pragma unroll 1
    for (int c = 0; c < 48; c++) {
        const float* rb = hp + c * P + y * W2 + x0;
        const float* w = wp + (k * S2K + c * 12) * 2;
#pragma unroll
        for (int dy = 0; dy < 3; dy++) {
            const float* rr = rb + dy * W2;
            u64 F[NP + 1];
#pragma unroll
            for (int j = 0; j <= NP; j++) F[j] = lds2(rr + 2 * j);
            u64 t0 = lds2(w + (dy * 4 + 0) * 2);
            u64 t1 = lds2(w + (dy * 4 + 1) * 2);
            u64 t2 = lds2(w + (dy * 4 + 2) * 2);
#pragma unroll
            for (int p = 0; p < NP; p++) {
                float alo, ahi, blo, bhi;
                unpack2(F[p], alo, ahi); unpack2(F[p + 1], blo, bhi);
                u64 M = pack2(ahi, blo);
                fma2(acc[p], t0, F[p]); fma2(acc[p], t1, M); fma2(acc[p], t2, F[p + 1]);
            }
        }
    }
    float* zb = sm + OFF_RP + k * HW + y * W + x0;  // zbuf alias (rp dead here)
#pragma unroll
    for (int p = 0; p < NP; p++)
        *reinterpret_cast<u64*>(zb + 2 * p) = acc[p];
}

template<int H, int W>
__device__ void conv2(float* __restrict__ sm, int tid) {
    constexpr int PX0 = 2 * ((W + 3) / 4);        // even px count of first half
    constexpr int NP0 = PX0 / 2;
    constexpr int NP1 = (W - PX0) / 2;
    if (tid >= 12 * H) return;
    int k = tid / (2 * H);
    int rm = tid - k * 2 * H;
    int y = rm >> 1, half = rm & 1;
    if (half == 0) {
        conv2_half<H, W, NP0>(sm, k, y, 0);
    } else if constexpr (NP1 > 0) {
        conv2_half<H, W, (NP1 > 0 ? NP1 : 1)>(sm, k, y, PX0);
    }
}

// conv2 for 1x1 scale
__device__ void conv2_1(float* __restrict__ sm, int tid) {
    if (tid >= 6) return;
    int k = tid;
    const float* hp = sm + OFF_HID;
    const float* wp = sm + OFF_W2P;
    float a = sm[OFF_B2 + k];
#pragma unroll 1
    for (int c = 0; c < 48; c++) {
        const float* rb = hp + c * 9;
        const float* w = wp + (k * S2K + c * 12) * 2;
#pragma unroll
        for (int dy = 0; dy < 3; dy++)
#pragma unroll
            for (int dx = 0; dx < 3; dx++)
                a = fmaf(w[(dy * 4 + dx) * 2], rb[dy * 3 + dx], a);
    }
    sm[OFF_RP + k] = a;  // zbuf [k][1]
}

// ---------------- stage e: upsample z (H,W)->(16,16), f -= z ----------------
template<int H, int W>
__device__ void upsub(float* __restrict__ sm_f, const float* __restrict__ zbuf, int tid) {
    constexpr int HW = H * W;
    for (int idx = tid; idx < 1536; idx += NT) {
        int c = idx >> 8;
        int p = idx & 255;
        int Y = p >> 4, X = p & 15;
        int iy0, iy1, ix0, ix1; float wy0, wy1, wx0, wx1;
        lin_coef<H, 16>(Y, iy0, iy1, wy0, wy1);
        lin_coef<W, 16>(X, ix0, ix1, wx0, wx1);
        float v = bilerp(zbuf + c * HW, W, iy0, iy1, ix0, ix1, wy0, wy1, wx0, wx1);
        sm_f[idx] = __fadd_rn(sm_f[idx], -v);
    }
}

// ---------------- one scale ----------------
template<int SI, int H, int W>
__device__ void do_scale(float* __restrict__ sm,
                         const float* __restrict__ w1g, const float* __restrict__ b1g,
                         const float* __restrict__ w2g, const float* __restrict__ b2g,
                         float* __restrict__ outp, int tid, float shift8) {
    constexpr bool LAST = (SI == 7);
    if constexpr (!LAST) {
        load_stage<SI, H, W>(sm, w1g, b1g, w2g, b2g, tid);
        __syncthreads();
    }
    resize_fsq<SI, H, W>(sm + OFF_F, sm + OFF_RP, outp, tid, shift8);
    if constexpr (LAST) return;
    __syncthreads();
    if constexpr (H == 1) conv1_1(sm, tid); else conv1<H, W>(sm, tid);
    __syncthreads();
    if constexpr (H == 1) conv2_1(sm, tid); else conv2<H, W>(sm, tid);
    __syncthreads();
    upsub<H, W>(sm + OFF_F, sm + OFF_RP, tid);
    __syncthreads();
}

__global__ void __launch_bounds__(NT, 2)
var_tokenizer_kernel(const float* __restrict__ lat,
                     const float* __restrict__ w1, const float* __restrict__ b1,
                     const float* __restrict__ w2, const float* __restrict__ b2,
                     float* __restrict__ out) {
    extern __shared__ float sm[];
    int b   = blockIdx.x;
    int tid = threadIdx.x;

    const float4* src  = reinterpret_cast<const float4*>(lat + (size_t)b * 1536);
    float4*       dstf = reinterpret_cast<float4*>(sm + OFF_F);
    for (int i = tid; i < 384; i += NT) dstf[i] = src[i];

    constexpr float HL8 = (8.0f - 1.0f) * 1.0010000467300415039f / 2.0f;
    float ratio = __fdiv_rn(0.5f, HL8);
    float shift8 = (float)atanh((double)ratio);

    float* outb = out + (size_t)b * 3726;
    __syncthreads();

    do_scale<0, 1, 1>  (sm, w1, b1, w2, b2, outb + 0,    tid, shift8);
    do_scale<1, 2, 2>  (sm, w1, b1, w2, b2, outb + 6,    tid, shift8);
    do_scale<2, 4, 4>  (sm, w1, b1, w2, b2, outb + 30,   tid, shift8);
    do_scale<3, 6, 6>  (sm, w1, b1, w2, b2, outb + 126,  tid, shift8);
    do_scale<4, 8, 8>  (sm, w1, b1, w2, b2, outb + 342,  tid, shift8);
    do_scale<5, 10, 10>(sm, w1, b1, w2, b2, outb + 726,  tid, shift8);
    do_scale<6, 12, 12>(sm, w1, b1, w2, b2, outb + 1326, tid, shift8);
    do_scale<7, 16, 16>(sm, w1, b1, w2, b2, outb + 2190, tid, shift8);
}

extern "C" void kernel_launch(void* const* d_in, const int* in_sizes, int n_in,
                              void* d_out, int out_size) {
    const float* lat = (const float*)d_in[0];
    const float* w1  = (const float*)d_in[1];
    const float* b1  = (const float*)d_in[2];
    const float* w2  = (const float*)d_in[3];
    const float* b2  = (const float*)d_in[4];
    float* out = (float*)d_out;

    int B = in_sizes[0] / 1536;

    cudaFuncSetAttribute(var_tokenizer_kernel,
                         cudaFuncAttributeMaxDynamicSharedMemorySize, SMEM_BYTES);
    var_tokenizer_kernel<<<B, NT, SMEM_BYTES>>>(lat, w1, b1, w2, b2, out);
}